// round 2
// baseline (speedup 1.0000x reference)
#include <cuda_runtime.h>

#define NNODES 100000
#define HID 128
#define EPS 1e-5f

// Scratch (no cudaMalloc allowed). Declared as float4 so the 16B alignment
// required by red.global.add.v4.f32 is guaranteed.
// h0 = post-linear ("ori"), act = post-LN/ReLU, acc = layer-0 aggregation.
__device__ float4 g_h0 [(size_t)NNODES * HID / 4];
__device__ float4 g_act[(size_t)NNODES * HID / 4];
__device__ float4 g_acc[(size_t)NNODES * HID / 4];

// ---------------------------------------------------------------------------
// GEMM: out[n][j] = sum_k x[n][k] * W[j][k] + b[j]
// Block = 256 threads (8 warps), 32 rows per block, full 128 cols.
// W transposed into shared (padded stride 132 floats -> conflict-free, 16B
// aligned float4 column loads). Each warp: 4 rows, each thread: 4 cols.
// ---------------------------------------------------------------------------
extern __shared__ float smem_dyn[];
__global__ void gemm_bias_kernel(const float* __restrict__ x,
                                 const float* __restrict__ W,
                                 const float* __restrict__ b,
                                 float* __restrict__ out, int n)
{
    float4* Ws4 = (float4*)smem_dyn;            // [128][33] float4 (stride 132 f)
    float*  xs  = smem_dyn + 128 * 132;         // 32 rows * 128
    const int tid  = threadIdx.x;
    const int lane = tid & 31;
    const int warp = tid >> 5;
    const int row0 = blockIdx.x * 32;

    // Load W transposed: Ws[k*132 + j] = W[j*128 + k]
    for (int idx = tid; idx < HID * HID; idx += blockDim.x) {
        int j = idx >> 7, k = idx & 127;
        smem_dyn[k * 132 + j] = W[idx];
    }
    // Load 32 x-rows (coalesced)
    for (int idx = tid; idx < 32 * HID; idx += blockDim.x) {
        int r = idx >> 7, k = idx & 127;
        int row = row0 + r;
        xs[r * HID + k] = (row < n) ? x[(size_t)row * HID + k] : 0.f;
    }
    __syncthreads();

    const int r0 = warp * 4;
    float acc[4][4];
    #pragma unroll
    for (int i = 0; i < 4; i++)
        #pragma unroll
        for (int c = 0; c < 4; c++) acc[i][c] = 0.f;

    #pragma unroll 4
    for (int k = 0; k < HID; k++) {
        float4 w = Ws4[k * 33 + lane];
        #pragma unroll
        for (int i = 0; i < 4; i++) {
            float xv = xs[(r0 + i) * HID + k];   // broadcast, conflict-free
            acc[i][0] += xv * w.x;
            acc[i][1] += xv * w.y;
            acc[i][2] += xv * w.z;
            acc[i][3] += xv * w.w;
        }
    }

    const int j0 = lane * 4;
    float4 bv = *(const float4*)&b[j0];
    #pragma unroll
    for (int i = 0; i < 4; i++) {
        int row = row0 + r0 + i;
        if (row < n) {
            float4 o;
            o.x = acc[i][0] + bv.x;
            o.y = acc[i][1] + bv.y;
            o.z = acc[i][2] + bv.z;
            o.w = acc[i][3] + bv.w;
            *(float4*)&out[(size_t)row * HID + j0] = o;
        }
    }
}

// ---------------------------------------------------------------------------
// Fused (optional residual) + LayerNorm + ReLU. Warp per row, float4 per lane.
// ---------------------------------------------------------------------------
__global__ void ln_relu_kernel(const float* __restrict__ hin,
                               const float* __restrict__ res,   // may be null
                               const float* __restrict__ scale,
                               const float* __restrict__ bias,
                               float* __restrict__ hout, int n)
{
    int row  = (blockIdx.x * blockDim.x + threadIdx.x) >> 5;
    int lane = threadIdx.x & 31;
    if (row >= n) return;
    size_t base = (size_t)row * HID + lane * 4;

    float4 v = *(const float4*)&hin[base];
    if (res) {
        float4 r = *(const float4*)&res[base];
        v.x += r.x; v.y += r.y; v.z += r.z; v.w += r.w;
    }
    float s = v.x + v.y + v.z + v.w;
    #pragma unroll
    for (int o = 16; o > 0; o >>= 1) s += __shfl_xor_sync(0xffffffffu, s, o);
    float mu = s * (1.f / HID);

    float dx = v.x - mu, dy = v.y - mu, dz = v.z - mu, dw = v.w - mu;
    float q = dx * dx + dy * dy + dz * dz + dw * dw;
    #pragma unroll
    for (int o = 16; o > 0; o >>= 1) q += __shfl_xor_sync(0xffffffffu, q, o);
    float rstd = rsqrtf(q * (1.f / HID) + EPS);

    int j = lane * 4;
    float4 sc = *(const float4*)&scale[j];
    float4 bi = *(const float4*)&bias[j];
    float4 o;
    o.x = fmaxf(dx * rstd * sc.x + bi.x, 0.f);
    o.y = fmaxf(dy * rstd * sc.y + bi.y, 0.f);
    o.z = fmaxf(dz * rstd * sc.z + bi.z, 0.f);
    o.w = fmaxf(dw * rstd * sc.w + bi.w, 0.f);
    *(float4*)&hout[base] = o;
}

// ---------------------------------------------------------------------------
// Zero an accumulator buffer (d_out is poisoned; scatter needs zeros).
// ---------------------------------------------------------------------------
__global__ void zero_kernel(float4* __restrict__ p, int n4)
{
    int i = blockIdx.x * blockDim.x + threadIdx.x;
    if (i < n4) p[i] = make_float4(0.f, 0.f, 0.f, 0.f);
}

// ---------------------------------------------------------------------------
// SpMM scatter: hout[dst] += hin[src] * e_feat[e].  One warp per edge.
// edge_index is INT32 (JAX x64 disabled downcasts int64 -> int32).
// Each lane: one float4 gather + one red.global.add.v4.f32 (vectorized
// no-return reduction, sm_90+) -> 32 REDs per edge, not 128 scalar atomics.
// ---------------------------------------------------------------------------
__global__ void spmm_kernel(const int* __restrict__ ei_src,
                            const int* __restrict__ ei_dst,
                            const float* __restrict__ ef,
                            const float* __restrict__ hin,
                            float* __restrict__ hout, int E)
{
    int e    = (blockIdx.x * blockDim.x + threadIdx.x) >> 5;
    int lane = threadIdx.x & 31;
    if (e >= E) return;

    int   src = __ldg(&ei_src[e]);
    int   dst = __ldg(&ei_dst[e]);
    float w   = __ldg(&ef[e]);

    const float4* in4 = (const float4*)(hin + (size_t)src * HID);
    float4 v = __ldg(&in4[lane]);

    float* outp = hout + (size_t)dst * HID + lane * 4;
    asm volatile("red.global.add.v4.f32 [%0], {%1, %2, %3, %4};"
                 :: "l"(outp), "f"(v.x * w), "f"(v.y * w), "f"(v.z * w), "f"(v.w * w)
                 : "memory");
}

// ---------------------------------------------------------------------------
extern "C" void kernel_launch(void* const* d_in, const int* in_sizes, int n_in,
                              void* d_out, int out_size)
{
    const float* x   = (const float*)d_in[0];
    const int*   ei  = (const int*)d_in[1];     // [2, E] int32
    const float* ef  = (const float*)d_in[2];
    const float* W   = (const float*)d_in[3];
    const float* b   = (const float*)d_in[4];
    const float* lns = (const float*)d_in[5];
    const float* lnb = (const float*)d_in[6];

    const int n = in_sizes[0] / HID;   // nodes
    const int E = in_sizes[2];         // edges
    float* out  = (float*)d_out;

    float4 *h0_4, *act_4, *acc_4;
    cudaGetSymbolAddress((void**)&h0_4,  g_h0);
    cudaGetSymbolAddress((void**)&act_4, g_act);
    cudaGetSymbolAddress((void**)&acc_4, g_acc);
    float* h0  = (float*)h0_4;
    float* act = (float*)act_4;
    float* acc = (float*)acc_4;

    // 1. Linear: h0 = x @ W^T + b
    const int gemm_smem = (128 * 132 + 32 * HID) * (int)sizeof(float); // 83968 B
    cudaFuncSetAttribute(gemm_bias_kernel,
                         cudaFuncAttributeMaxDynamicSharedMemorySize, gemm_smem);
    gemm_bias_kernel<<<(n + 31) / 32, 256, gemm_smem>>>(x, W, b, h0, n);

    const int ln_blocks   = (n + 7) / 8;          // 8 warps (rows) per block
    const int n4          = n * HID / 4;
    const int zero_blocks = (n4 + 255) / 256;
    const int spmm_blocks = (E + 7) / 8;          // 8 edges (warps) per block

    // 2. Layer 0: LN + ReLU, then scatter into acc
    ln_relu_kernel<<<ln_blocks, 256>>>(h0, nullptr, lns, lnb, act, n);
    zero_kernel<<<zero_blocks, 256>>>((float4*)acc, n4);
    spmm_kernel<<<spmm_blocks, 256>>>(ei, ei + E, ef, act, acc, E);

    // 3. Layer 1: residual + LN + ReLU, then scatter into d_out
    ln_relu_kernel<<<ln_blocks, 256>>>(acc, h0, lns + HID, lnb + HID, act, n);
    zero_kernel<<<zero_blocks, 256>>>((float4*)out, n4);
    spmm_kernel<<<spmm_blocks, 256>>>(ei, ei + E, ef, act, out, E);
}

// round 4
// speedup vs baseline: 1.1556x; 1.1556x over previous
#include <cuda_runtime.h>

#define NMAX 100000
#define EMAX 1600000
#define HID 128
#define EPS 1e-5f

// Scratch (no cudaMalloc allowed). float4 arrays guarantee 16B alignment.
__device__ float4 g_h0  [(size_t)NMAX * HID / 4];  // post-linear ("ori")
__device__ float4 g_act [(size_t)NMAX * HID / 4];  // layer-0 input (post LN+ReLU)
__device__ float4 g_act2[(size_t)NMAX * HID / 4];  // layer-1 input
__device__ int2   g_srcw[EMAX];                    // CSR payload: (src, w-bits)
__device__ int    g_off [NMAX + 1];
__device__ int    g_cur [NMAX];
__device__ int    g_deg [NMAX];

// ---------------------------------------------------------------------------
// GEMM + bias, fused LayerNorm(scale0,bias0) + ReLU epilogue.
// Writes h0 (pre-LN, for the residual) and act (post LN+ReLU).
// Block = 256 threads, 32 rows; warp: 4 rows, lane: 4 cols.
// ---------------------------------------------------------------------------
extern __shared__ float smem_dyn[];
__global__ void gemm_ln_kernel(const float* __restrict__ x,
                               const float* __restrict__ W,
                               const float* __restrict__ b,
                               const float* __restrict__ lns,
                               const float* __restrict__ lnb,
                               float* __restrict__ h0,
                               float* __restrict__ act, int n)
{
    float4* Ws4 = (float4*)smem_dyn;            // [128][33] float4 (stride 132 f)
    float*  xs  = smem_dyn + 128 * 132;         // 32 rows * 128
    const int tid  = threadIdx.x;
    const int lane = tid & 31;
    const int warp = tid >> 5;
    const int row0 = blockIdx.x * 32;

    // W transposed into smem: Ws[k*132 + j] = W[j*128 + k]
    for (int idx = tid; idx < HID * HID; idx += blockDim.x) {
        int j = idx >> 7, k = idx & 127;
        smem_dyn[k * 132 + j] = W[idx];
    }
    for (int idx = tid; idx < 32 * HID; idx += blockDim.x) {
        int r = idx >> 7, k = idx & 127;
        int row = row0 + r;
        xs[r * HID + k] = (row < n) ? x[(size_t)row * HID + k] : 0.f;
    }
    __syncthreads();

    const int r0 = warp * 4;
    float acc[4][4];
    #pragma unroll
    for (int i = 0; i < 4; i++)
        #pragma unroll
        for (int c = 0; c < 4; c++) acc[i][c] = 0.f;

    #pragma unroll 2
    for (int k0 = 0; k0 < HID; k0 += 4) {
        float4 w0 = Ws4[(k0 + 0) * 33 + lane];
        float4 w1 = Ws4[(k0 + 1) * 33 + lane];
        float4 w2 = Ws4[(k0 + 2) * 33 + lane];
        float4 w3 = Ws4[(k0 + 3) * 33 + lane];
        #pragma unroll
        for (int i = 0; i < 4; i++) {
            float4 xv = *(const float4*)&xs[(r0 + i) * HID + k0];  // broadcast
            acc[i][0] += xv.x * w0.x; acc[i][0] += xv.y * w1.x;
            acc[i][0] += xv.z * w2.x; acc[i][0] += xv.w * w3.x;
            acc[i][1] += xv.x * w0.y; acc[i][1] += xv.y * w1.y;
            acc[i][1] += xv.z * w2.y; acc[i][1] += xv.w * w3.y;
            acc[i][2] += xv.x * w0.z; acc[i][2] += xv.y * w1.z;
            acc[i][2] += xv.z * w2.z; acc[i][2] += xv.w * w3.z;
            acc[i][3] += xv.x * w0.w; acc[i][3] += xv.y * w1.w;
            acc[i][3] += xv.z * w2.w; acc[i][3] += xv.w * w3.w;
        }
    }

    const int j0 = lane * 4;
    float4 bv = *(const float4*)&b[j0];
    float4 sc = *(const float4*)&lns[j0];
    float4 bi = *(const float4*)&lnb[j0];

    #pragma unroll
    for (int i = 0; i < 4; i++) {
        int row = row0 + r0 + i;              // uniform across the warp
        if (row < n) {
            float4 h;
            h.x = acc[i][0] + bv.x; h.y = acc[i][1] + bv.y;
            h.z = acc[i][2] + bv.z; h.w = acc[i][3] + bv.w;
            *(float4*)&h0[(size_t)row * HID + j0] = h;

            float s = h.x + h.y + h.z + h.w;
            #pragma unroll
            for (int o = 16; o > 0; o >>= 1) s += __shfl_xor_sync(0xffffffffu, s, o);
            float mu = s * (1.f / HID);
            float dx = h.x - mu, dy = h.y - mu, dz = h.z - mu, dw = h.w - mu;
            float q = dx * dx + dy * dy + dz * dz + dw * dw;
            #pragma unroll
            for (int o = 16; o > 0; o >>= 1) q += __shfl_xor_sync(0xffffffffu, q, o);
            float rstd = rsqrtf(q * (1.f / HID) + EPS);

            float4 o4;
            o4.x = fmaxf(dx * rstd * sc.x + bi.x, 0.f);
            o4.y = fmaxf(dy * rstd * sc.y + bi.y, 0.f);
            o4.z = fmaxf(dz * rstd * sc.z + bi.z, 0.f);
            o4.w = fmaxf(dw * rstd * sc.w + bi.w, 0.f);
            *(float4*)&act[(size_t)row * HID + j0] = o4;
        }
    }
}

// ---------------------------------------------------------------------------
// CSR build
// ---------------------------------------------------------------------------
__global__ void zero_deg_kernel(int* __restrict__ deg, int n)
{
    int i = blockIdx.x * blockDim.x + threadIdx.x;
    if (i < n) deg[i] = 0;
}

__global__ void hist_kernel(const int* __restrict__ dst, int* __restrict__ deg, int E)
{
    int e = blockIdx.x * blockDim.x + threadIdx.x;
    if (e < E) atomicAdd(&deg[dst[e]], 1);
}

// One block, 1024 threads: chunked exclusive scan of deg -> off, cur.
__global__ void scan_kernel(const int* __restrict__ deg,
                            int* __restrict__ off, int* __restrict__ cur, int n)
{
    __shared__ int part[1024];
    const int t = threadIdx.x;
    const int C = (n + 1023) >> 10;
    const int st = t * C;
    const int en = min(st + C, n);

    int s = 0;
    for (int i = st; i < en; i++) s += deg[i];
    part[t] = s;
    __syncthreads();

    // inclusive Hillis-Steele scan
    for (int o = 1; o < 1024; o <<= 1) {
        int u = (t >= o) ? part[t - o] : 0;
        __syncthreads();
        part[t] += u;
        __syncthreads();
    }
    int run = part[t] - s;   // exclusive base for this chunk
    for (int i = st; i < en; i++) {
        off[i] = run;
        cur[i] = run;
        run += deg[i];
    }
    if (t == 1023) off[n] = part[1023];
}

__global__ void fill_kernel(const int* __restrict__ src, const int* __restrict__ dst,
                            const float* __restrict__ ef,
                            int* __restrict__ cur, int2* __restrict__ srcw, int E)
{
    int e = blockIdx.x * blockDim.x + threadIdx.x;
    if (e < E) {
        int d = dst[e];
        int p = atomicAdd(&cur[d], 1);
        srcw[p] = make_int2(src[e], __float_as_int(ef[e]));
    }
}

// ---------------------------------------------------------------------------
// SpMM gather-reduce: warp per node, register accumulation, one store per row.
// FUSE_LN: out = relu(LN(acc + h0)) (layer-0 aggregation feeding layer 1).
// else:    out = acc (final output).
// ---------------------------------------------------------------------------
template <bool FUSE_LN>
__global__ void spmm_csr_kernel(const int* __restrict__ off,
                                const int2* __restrict__ srcw,
                                const float4* __restrict__ hin,
                                const float4* __restrict__ h0,
                                const float* __restrict__ lns,
                                const float* __restrict__ lnb,
                                float4* __restrict__ out, int n)
{
    const int node = blockIdx.x * 8 + (threadIdx.x >> 5);
    const int lane = threadIdx.x & 31;
    if (node >= n) return;

    const int beg = off[node];
    const int end = off[node + 1];

    float4 a = make_float4(0.f, 0.f, 0.f, 0.f);
    for (int base = beg; base < end; base += 32) {
        int rem = end - base;
        int cnt = min(rem, 32);
        int2 sw = make_int2(0, 0);
        if (lane < cnt) sw = __ldg(&srcw[base + lane]);
        #pragma unroll 4
        for (int j = 0; j < cnt; j++) {
            int   s = __shfl_sync(0xffffffffu, sw.x, j);
            float w = __int_as_float(__shfl_sync(0xffffffffu, sw.y, j));
            float4 v = __ldg(&hin[(size_t)s * 32 + lane]);
            a.x += v.x * w; a.y += v.y * w; a.z += v.z * w; a.w += v.w * w;
        }
    }

    if (FUSE_LN) {
        float4 r = __ldg(&h0[(size_t)node * 32 + lane]);
        a.x += r.x; a.y += r.y; a.z += r.z; a.w += r.w;

        float s = a.x + a.y + a.z + a.w;
        #pragma unroll
        for (int o = 16; o > 0; o >>= 1) s += __shfl_xor_sync(0xffffffffu, s, o);
        float mu = s * (1.f / HID);
        float dx = a.x - mu, dy = a.y - mu, dz = a.z - mu, dw = a.w - mu;
        float q = dx * dx + dy * dy + dz * dz + dw * dw;
        #pragma unroll
        for (int o = 16; o > 0; o >>= 1) q += __shfl_xor_sync(0xffffffffu, q, o);
        float rstd = rsqrtf(q * (1.f / HID) + EPS);

        int j0 = lane * 4;
        float4 sc = __ldg((const float4*)&lns[j0]);
        float4 bi = __ldg((const float4*)&lnb[j0]);
        float4 o4;
        o4.x = fmaxf(dx * rstd * sc.x + bi.x, 0.f);
        o4.y = fmaxf(dy * rstd * sc.y + bi.y, 0.f);
        o4.z = fmaxf(dz * rstd * sc.z + bi.z, 0.f);
        o4.w = fmaxf(dw * rstd * sc.w + bi.w, 0.f);
        out[(size_t)node * 32 + lane] = o4;
    } else {
        out[(size_t)node * 32 + lane] = a;
    }
}

// ---------------------------------------------------------------------------
extern "C" void kernel_launch(void* const* d_in, const int* in_sizes, int n_in,
                              void* d_out, int out_size)
{
    const float* x   = (const float*)d_in[0];
    const int*   ei  = (const int*)d_in[1];     // [2, E] int32
    const float* ef  = (const float*)d_in[2];
    const float* W   = (const float*)d_in[3];
    const float* b   = (const float*)d_in[4];
    const float* lns = (const float*)d_in[5];
    const float* lnb = (const float*)d_in[6];

    const int n = in_sizes[0] / HID;
    const int E = in_sizes[2];
    float4* out = (float4*)d_out;

    float4 *h0, *act, *act2; int2* srcw; int *off, *cur, *deg;
    cudaGetSymbolAddress((void**)&h0,   g_h0);
    cudaGetSymbolAddress((void**)&act,  g_act);
    cudaGetSymbolAddress((void**)&act2, g_act2);
    cudaGetSymbolAddress((void**)&srcw, g_srcw);
    cudaGetSymbolAddress((void**)&off,  g_off);
    cudaGetSymbolAddress((void**)&cur,  g_cur);
    cudaGetSymbolAddress((void**)&deg,  g_deg);

    // 1. Linear + LN0 + ReLU (fused)
    const int gemm_smem = (128 * 132 + 32 * HID) * (int)sizeof(float); // 83968 B
    cudaFuncSetAttribute(gemm_ln_kernel,
                         cudaFuncAttributeMaxDynamicSharedMemorySize, gemm_smem);
    gemm_ln_kernel<<<(n + 31) / 32, 256, gemm_smem>>>(x, W, b, lns, lnb,
                                                      (float*)h0, (float*)act, n);

    // 2. CSR build (dst-grouped)
    zero_deg_kernel<<<(n + 255) / 256, 256>>>(deg, n);
    hist_kernel<<<(E + 255) / 256, 256>>>(ei + E, deg, E);
    scan_kernel<<<1, 1024>>>(deg, off, cur, n);
    fill_kernel<<<(E + 255) / 256, 256>>>(ei, ei + E, ef, cur, srcw, E);

    // 3. Layer 0 aggregation + residual + LN1 + ReLU (fused)
    const int spmm_blocks = (n + 7) / 8;
    spmm_csr_kernel<true><<<spmm_blocks, 256>>>(off, srcw, act, h0,
                                                lns + HID, lnb + HID, act2, n);

    // 4. Layer 1 aggregation -> final output
    spmm_csr_kernel<false><<<spmm_blocks, 256>>>(off, srcw, act2, nullptr,
                                                 nullptr, nullptr, out, n);
}

// round 6
// speedup vs baseline: 1.6199x; 1.4017x over previous
#include <cuda_runtime.h>

#define NMAX 100000
#define EMAX 1600000
#define HID 128
#define EPS 1e-5f
#define CHUNK 1024          // elements of deg per scan block
#define NBLK ((NMAX + CHUNK - 1) / CHUNK)   // 98

// Scratch (no cudaMalloc allowed). float4 arrays guarantee 16B alignment.
__device__ float4 g_h0  [(size_t)NMAX * HID / 4];  // post-linear ("ori")
__device__ float4 g_act [(size_t)NMAX * HID / 4];  // layer-0 input (post LN+ReLU)
__device__ float4 g_act2[(size_t)NMAX * HID / 4];  // layer-1 input
__device__ int2   g_srcw[EMAX];                    // CSR payload: (src, w-bits)
__device__ int    g_off [NMAX + 1];
__device__ int    g_cur [NMAX];
__device__ int    g_deg [NMAX];
__device__ int    g_bsum[NBLK + 1];

// ---------------------------------------------------------------------------
// GEMM + bias, fused LayerNorm(scale0,bias0) + ReLU epilogue.
// Writes h0 (pre-LN, for the residual) and act (post LN+ReLU).
// Block = 256 threads, 32 rows; warp: 4 rows, lane: 4 cols.
// ---------------------------------------------------------------------------
extern __shared__ float smem_dyn[];
__global__ void gemm_ln_kernel(const float* __restrict__ x,
                               const float* __restrict__ W,
                               const float* __restrict__ b,
                               const float* __restrict__ lns,
                               const float* __restrict__ lnb,
                               float* __restrict__ h0,
                               float* __restrict__ act, int n)
{
    float4* Ws4 = (float4*)smem_dyn;            // [128][33] float4 (stride 132 f)
    float*  xs  = smem_dyn + 128 * 132;         // 32 rows * 128
    const int tid  = threadIdx.x;
    const int lane = tid & 31;
    const int warp = tid >> 5;
    const int row0 = blockIdx.x * 32;

    for (int idx = tid; idx < HID * HID; idx += blockDim.x) {
        int j = idx >> 7, k = idx & 127;
        smem_dyn[k * 132 + j] = W[idx];
    }
    for (int idx = tid; idx < 32 * HID; idx += blockDim.x) {
        int r = idx >> 7, k = idx & 127;
        int row = row0 + r;
        xs[r * HID + k] = (row < n) ? x[(size_t)row * HID + k] : 0.f;
    }
    __syncthreads();

    const int r0 = warp * 4;
    float acc[4][4];
    #pragma unroll
    for (int i = 0; i < 4; i++)
        #pragma unroll
        for (int c = 0; c < 4; c++) acc[i][c] = 0.f;

    #pragma unroll 2
    for (int k0 = 0; k0 < HID; k0 += 4) {
        float4 w0 = Ws4[(k0 + 0) * 33 + lane];
        float4 w1 = Ws4[(k0 + 1) * 33 + lane];
        float4 w2 = Ws4[(k0 + 2) * 33 + lane];
        float4 w3 = Ws4[(k0 + 3) * 33 + lane];
        #pragma unroll
        for (int i = 0; i < 4; i++) {
            float4 xv = *(const float4*)&xs[(r0 + i) * HID + k0];
            acc[i][0] += xv.x * w0.x; acc[i][0] += xv.y * w1.x;
            acc[i][0] += xv.z * w2.x; acc[i][0] += xv.w * w3.x;
            acc[i][1] += xv.x * w0.y; acc[i][1] += xv.y * w1.y;
            acc[i][1] += xv.z * w2.y; acc[i][1] += xv.w * w3.y;
            acc[i][2] += xv.x * w0.z; acc[i][2] += xv.y * w1.z;
            acc[i][2] += xv.z * w2.z; acc[i][2] += xv.w * w3.z;
            acc[i][3] += xv.x * w0.w; acc[i][3] += xv.y * w1.w;
            acc[i][3] += xv.z * w2.w; acc[i][3] += xv.w * w3.w;
        }
    }

    const int j0 = lane * 4;
    float4 bv = *(const float4*)&b[j0];
    float4 sc = *(const float4*)&lns[j0];
    float4 bi = *(const float4*)&lnb[j0];

    #pragma unroll
    for (int i = 0; i < 4; i++) {
        int row = row0 + r0 + i;
        if (row < n) {
            float4 h;
            h.x = acc[i][0] + bv.x; h.y = acc[i][1] + bv.y;
            h.z = acc[i][2] + bv.z; h.w = acc[i][3] + bv.w;
            *(float4*)&h0[(size_t)row * HID + j0] = h;

            float s = h.x + h.y + h.z + h.w;
            #pragma unroll
            for (int o = 16; o > 0; o >>= 1) s += __shfl_xor_sync(0xffffffffu, s, o);
            float mu = s * (1.f / HID);
            float dx = h.x - mu, dy = h.y - mu, dz = h.z - mu, dw = h.w - mu;
            float q = dx * dx + dy * dy + dz * dz + dw * dw;
            #pragma unroll
            for (int o = 16; o > 0; o >>= 1) q += __shfl_xor_sync(0xffffffffu, q, o);
            float rstd = rsqrtf(q * (1.f / HID) + EPS);

            float4 o4;
            o4.x = fmaxf(dx * rstd * sc.x + bi.x, 0.f);
            o4.y = fmaxf(dy * rstd * sc.y + bi.y, 0.f);
            o4.z = fmaxf(dz * rstd * sc.z + bi.z, 0.f);
            o4.w = fmaxf(dw * rstd * sc.w + bi.w, 0.f);
            *(float4*)&act[(size_t)row * HID + j0] = o4;
        }
    }
}

// ---------------------------------------------------------------------------
// CSR build
// ---------------------------------------------------------------------------
__global__ void zero_deg_kernel(int* __restrict__ deg, int n)
{
    int i = blockIdx.x * blockDim.x + threadIdx.x;
    if (i < n) deg[i] = 0;
}

__global__ void hist_kernel(const int* __restrict__ dst, int* __restrict__ deg, int E)
{
    int e = blockIdx.x * blockDim.x + threadIdx.x;
    if (e < E) atomicAdd(&deg[dst[e]], 1);
}

// Phase 1: block b sums deg[b*CHUNK .. b*CHUNK+CHUNK) -> bsum[b].
__global__ void reduce_kernel(const int* __restrict__ deg,
                              int* __restrict__ bsum, int n)
{
    __shared__ int sh[256];
    const int t = threadIdx.x;
    const int base = blockIdx.x * CHUNK;
    int s = 0;
    #pragma unroll
    for (int j = 0; j < CHUNK / 256; j++) {
        int i = base + j * 256 + t;
        if (i < n) s += deg[i];
    }
    sh[t] = s;
    __syncthreads();
    #pragma unroll
    for (int o = 128; o > 0; o >>= 1) {
        if (t < o) sh[t] += sh[t + o];
        __syncthreads();
    }
    if (t == 0) bsum[blockIdx.x] = sh[0];
}

// Phase 2: one block scans nb (<=128) block sums -> exclusive bases in place.
__global__ void scan_bsum_kernel(int* __restrict__ bsum, int nb)
{
    __shared__ int sh[128];
    const int t = threadIdx.x;
    int v = (t < nb) ? bsum[t] : 0;
    sh[t] = v;
    __syncthreads();
    for (int o = 1; o < 128; o <<= 1) {
        int u = (t >= o) ? sh[t - o] : 0;
        __syncthreads();
        sh[t] += u;
        __syncthreads();
    }
    if (t < nb) bsum[t] = sh[t] - v;        // exclusive
    if (t == nb - 1) bsum[nb] = sh[t];      // total
}

// Phase 3: block b scans its chunk (256 threads x 4 elems) and writes off/cur.
__global__ void write_off_kernel(const int* __restrict__ deg,
                                 const int* __restrict__ bsum,
                                 int* __restrict__ off,
                                 int* __restrict__ cur, int n, int nb)
{
    __shared__ int sh[256];
    const int t = threadIdx.x;
    const int base = blockIdx.x * CHUNK + t * 4;

    int d[4];
    #pragma unroll
    for (int j = 0; j < 4; j++)
        d[j] = (base + j < n) ? deg[base + j] : 0;

    int local = d[0] + d[1] + d[2] + d[3];
    sh[t] = local;
    __syncthreads();
    for (int o = 1; o < 256; o <<= 1) {
        int u = (t >= o) ? sh[t - o] : 0;
        __syncthreads();
        sh[t] += u;
        __syncthreads();
    }
    int run = bsum[blockIdx.x] + sh[t] - local;   // exclusive base for elem 0
    #pragma unroll
    for (int j = 0; j < 4; j++) {
        int i = base + j;
        if (i < n) { off[i] = run; cur[i] = run; run += d[j]; }
    }
    if (blockIdx.x == 0 && t == 0) off[n] = bsum[nb];
}

__global__ void fill_kernel(const int* __restrict__ src, const int* __restrict__ dst,
                            const float* __restrict__ ef,
                            int* __restrict__ cur, int2* __restrict__ srcw, int E)
{
    int e = blockIdx.x * blockDim.x + threadIdx.x;
    if (e < E) {
        int d = dst[e];
        int p = atomicAdd(&cur[d], 1);
        srcw[p] = make_int2(src[e], __float_as_int(ef[e]));
    }
}

// ---------------------------------------------------------------------------
// SpMM gather-reduce: warp per node, register accumulation, one store per row.
// FUSE_LN: out = relu(LN(acc + h0)) (layer-0 aggregation feeding layer 1).
// else:    out = acc (final output).
// ---------------------------------------------------------------------------
template <bool FUSE_LN>
__global__ void spmm_csr_kernel(const int* __restrict__ off,
                                const int2* __restrict__ srcw,
                                const float4* __restrict__ hin,
                                const float4* __restrict__ h0,
                                const float* __restrict__ lns,
                                const float* __restrict__ lnb,
                                float4* __restrict__ out, int n)
{
    const int node = blockIdx.x * 8 + (threadIdx.x >> 5);
    const int lane = threadIdx.x & 31;
    if (node >= n) return;

    const int beg = off[node];
    const int end = off[node + 1];

    float4 a = make_float4(0.f, 0.f, 0.f, 0.f);
    for (int base = beg; base < end; base += 32) {
        int rem = end - base;
        int cnt = min(rem, 32);
        int2 sw = make_int2(0, 0);
        if (lane < cnt) sw = __ldg(&srcw[base + lane]);
        #pragma unroll 4
        for (int j = 0; j < cnt; j++) {
            int   s = __shfl_sync(0xffffffffu, sw.x, j);
            float w = __int_as_float(__shfl_sync(0xffffffffu, sw.y, j));
            float4 v = __ldg(&hin[(size_t)s * 32 + lane]);
            a.x += v.x * w; a.y += v.y * w; a.z += v.z * w; a.w += v.w * w;
        }
    }

    if (FUSE_LN) {
        float4 r = __ldg(&h0[(size_t)node * 32 + lane]);
        a.x += r.x; a.y += r.y; a.z += r.z; a.w += r.w;

        float s = a.x + a.y + a.z + a.w;
        #pragma unroll
        for (int o = 16; o > 0; o >>= 1) s += __shfl_xor_sync(0xffffffffu, s, o);
        float mu = s * (1.f / HID);
        float dx = a.x - mu, dy = a.y - mu, dz = a.z - mu, dw = a.w - mu;
        float q = dx * dx + dy * dy + dz * dz + dw * dw;
        #pragma unroll
        for (int o = 16; o > 0; o >>= 1) q += __shfl_xor_sync(0xffffffffu, q, o);
        float rstd = rsqrtf(q * (1.f / HID) + EPS);

        int j0 = lane * 4;
        float4 sc = __ldg((const float4*)&lns[j0]);
        float4 bi = __ldg((const float4*)&lnb[j0]);
        float4 o4;
        o4.x = fmaxf(dx * rstd * sc.x + bi.x, 0.f);
        o4.y = fmaxf(dy * rstd * sc.y + bi.y, 0.f);
        o4.z = fmaxf(dz * rstd * sc.z + bi.z, 0.f);
        o4.w = fmaxf(dw * rstd * sc.w + bi.w, 0.f);
        out[(size_t)node * 32 + lane] = o4;
    } else {
        out[(size_t)node * 32 + lane] = a;
    }
}

// ---------------------------------------------------------------------------
extern "C" void kernel_launch(void* const* d_in, const int* in_sizes, int n_in,
                              void* d_out, int out_size)
{
    const float* x   = (const float*)d_in[0];
    const int*   ei  = (const int*)d_in[1];     // [2, E] int32
    const float* ef  = (const float*)d_in[2];
    const float* W   = (const float*)d_in[3];
    const float* b   = (const float*)d_in[4];
    const float* lns = (const float*)d_in[5];
    const float* lnb = (const float*)d_in[6];

    const int n = in_sizes[0] / HID;
    const int E = in_sizes[2];
    float4* out = (float4*)d_out;

    float4 *h0, *act, *act2; int2* srcw; int *off, *cur, *deg, *bsum;
    cudaGetSymbolAddress((void**)&h0,   g_h0);
    cudaGetSymbolAddress((void**)&act,  g_act);
    cudaGetSymbolAddress((void**)&act2, g_act2);
    cudaGetSymbolAddress((void**)&srcw, g_srcw);
    cudaGetSymbolAddress((void**)&off,  g_off);
    cudaGetSymbolAddress((void**)&cur,  g_cur);
    cudaGetSymbolAddress((void**)&deg,  g_deg);
    cudaGetSymbolAddress((void**)&bsum, g_bsum);

    const int nb = (n + CHUNK - 1) / CHUNK;      // <= 98 for n=100K

    // 1. Linear + LN0 + ReLU (fused)
    const int gemm_smem = (128 * 132 + 32 * HID) * (int)sizeof(float); // 83968 B
    cudaFuncSetAttribute(gemm_ln_kernel,
                         cudaFuncAttributeMaxDynamicSharedMemorySize, gemm_smem);
    gemm_ln_kernel<<<(n + 31) / 32, 256, gemm_smem>>>(x, W, b, lns, lnb,
                                                      (float*)h0, (float*)act, n);

    // 2. CSR build (dst-grouped), fully parallel scan
    zero_deg_kernel<<<(n + 255) / 256, 256>>>(deg, n);
    hist_kernel<<<(E + 255) / 256, 256>>>(ei + E, deg, E);
    reduce_kernel<<<nb, 256>>>(deg, bsum, n);
    scan_bsum_kernel<<<1, 128>>>(bsum, nb);
    write_off_kernel<<<nb, 256>>>(deg, bsum, off, cur, n, nb);
    fill_kernel<<<(E + 255) / 256, 256>>>(ei, ei + E, ef, cur, srcw, E);

    // 3. Layer 0 aggregation + residual + LN1 + ReLU (fused)
    const int spmm_blocks = (n + 7) / 8;
    spmm_csr_kernel<true><<<spmm_blocks, 256>>>(off, srcw, act, h0,
                                                lns + HID, lnb + HID, act2, n);

    // 4. Layer 1 aggregation -> final output
    spmm_csr_kernel<false><<<spmm_blocks, 256>>>(off, srcw, act2, nullptr,
                                                 nullptr, nullptr, out, n);
}

// round 7
// speedup vs baseline: 1.8420x; 1.1371x over previous
#include <cuda_runtime.h>
#include <cuda_fp16.h>

#define NMAX 100000
#define EMAX 1600000
#define HID 128
#define EPS 1e-5f
#define CHUNK 1024
#define NBLK ((NMAX + CHUNK - 1) / CHUNK)   // 98

// Scratch (no cudaMalloc allowed).
__device__ float4 g_h0  [(size_t)NMAX * HID / 4];  // post-linear ("ori"), fp32
__device__ uint2  g_act [(size_t)NMAX * HID / 4];  // layer-0 input, fp16 (4 halfs/uint2)
__device__ uint2  g_act2[(size_t)NMAX * HID / 4];  // layer-1 input, fp16
__device__ int2   g_srcw[EMAX];                    // CSR payload: (src, w-bits)
__device__ int    g_off [NMAX + 1];
__device__ int    g_cur [NMAX];
__device__ int    g_deg [NMAX];
__device__ int    g_bsum[NBLK + 1];

// Pack 4 floats -> 4 halfs (uint2)
__device__ __forceinline__ uint2 pack_h4(float a, float b, float c, float d)
{
    uint2 r;
    half2 lo = __floats2half2_rn(a, b);
    half2 hi = __floats2half2_rn(c, d);
    r.x = *(unsigned*)&lo;
    r.y = *(unsigned*)&hi;
    return r;
}

// ---------------------------------------------------------------------------
// GEMM + bias, fused LayerNorm(scale0,bias0) + ReLU epilogue.
// Writes h0 (fp32, pre-LN residual) and act (fp16, post LN+ReLU).
// ---------------------------------------------------------------------------
extern __shared__ float smem_dyn[];
__global__ void gemm_ln_kernel(const float* __restrict__ x,
                               const float* __restrict__ W,
                               const float* __restrict__ b,
                               const float* __restrict__ lns,
                               const float* __restrict__ lnb,
                               float* __restrict__ h0,
                               uint2* __restrict__ act, int n)
{
    float4* Ws4 = (float4*)smem_dyn;            // [128][33] float4 (stride 132 f)
    float*  xs  = smem_dyn + 128 * 132;         // 32 rows * 128
    const int tid  = threadIdx.x;
    const int lane = tid & 31;
    const int warp = tid >> 5;
    const int row0 = blockIdx.x * 32;

    for (int idx = tid; idx < HID * HID; idx += blockDim.x) {
        int j = idx >> 7, k = idx & 127;
        smem_dyn[k * 132 + j] = W[idx];
    }
    for (int idx = tid; idx < 32 * HID; idx += blockDim.x) {
        int r = idx >> 7, k = idx & 127;
        int row = row0 + r;
        xs[r * HID + k] = (row < n) ? x[(size_t)row * HID + k] : 0.f;
    }
    __syncthreads();

    const int r0 = warp * 4;
    float acc[4][4];
    #pragma unroll
    for (int i = 0; i < 4; i++)
        #pragma unroll
        for (int c = 0; c < 4; c++) acc[i][c] = 0.f;

    #pragma unroll 2
    for (int k0 = 0; k0 < HID; k0 += 4) {
        float4 w0 = Ws4[(k0 + 0) * 33 + lane];
        float4 w1 = Ws4[(k0 + 1) * 33 + lane];
        float4 w2 = Ws4[(k0 + 2) * 33 + lane];
        float4 w3 = Ws4[(k0 + 3) * 33 + lane];
        #pragma unroll
        for (int i = 0; i < 4; i++) {
            float4 xv = *(const float4*)&xs[(r0 + i) * HID + k0];
            acc[i][0] += xv.x * w0.x; acc[i][0] += xv.y * w1.x;
            acc[i][0] += xv.z * w2.x; acc[i][0] += xv.w * w3.x;
            acc[i][1] += xv.x * w0.y; acc[i][1] += xv.y * w1.y;
            acc[i][1] += xv.z * w2.y; acc[i][1] += xv.w * w3.y;
            acc[i][2] += xv.x * w0.z; acc[i][2] += xv.y * w1.z;
            acc[i][2] += xv.z * w2.z; acc[i][2] += xv.w * w3.z;
            acc[i][3] += xv.x * w0.w; acc[i][3] += xv.y * w1.w;
            acc[i][3] += xv.z * w2.w; acc[i][3] += xv.w * w3.w;
        }
    }

    const int j0 = lane * 4;
    float4 bv = *(const float4*)&b[j0];
    float4 sc = *(const float4*)&lns[j0];
    float4 bi = *(const float4*)&lnb[j0];

    #pragma unroll
    for (int i = 0; i < 4; i++) {
        int row = row0 + r0 + i;
        if (row < n) {
            float4 h;
            h.x = acc[i][0] + bv.x; h.y = acc[i][1] + bv.y;
            h.z = acc[i][2] + bv.z; h.w = acc[i][3] + bv.w;
            *(float4*)&h0[(size_t)row * HID + j0] = h;

            float s = h.x + h.y + h.z + h.w;
            #pragma unroll
            for (int o = 16; o > 0; o >>= 1) s += __shfl_xor_sync(0xffffffffu, s, o);
            float mu = s * (1.f / HID);
            float dx = h.x - mu, dy = h.y - mu, dz = h.z - mu, dw = h.w - mu;
            float q = dx * dx + dy * dy + dz * dz + dw * dw;
            #pragma unroll
            for (int o = 16; o > 0; o >>= 1) q += __shfl_xor_sync(0xffffffffu, q, o);
            float rstd = rsqrtf(q * (1.f / HID) + EPS);

            act[(size_t)row * 32 + lane] = pack_h4(
                fmaxf(dx * rstd * sc.x + bi.x, 0.f),
                fmaxf(dy * rstd * sc.y + bi.y, 0.f),
                fmaxf(dz * rstd * sc.z + bi.z, 0.f),
                fmaxf(dw * rstd * sc.w + bi.w, 0.f));
        }
    }
}

// ---------------------------------------------------------------------------
// CSR build
// ---------------------------------------------------------------------------
__global__ void zero_deg_kernel(int* __restrict__ deg, int n)
{
    int i = blockIdx.x * blockDim.x + threadIdx.x;
    if (i < n) deg[i] = 0;
}

__global__ void hist_kernel(const int* __restrict__ dst, int* __restrict__ deg, int E)
{
    int e = blockIdx.x * blockDim.x + threadIdx.x;
    if (e < E) atomicAdd(&deg[dst[e]], 1);
}

__global__ void reduce_kernel(const int* __restrict__ deg,
                              int* __restrict__ bsum, int n)
{
    __shared__ int sh[256];
    const int t = threadIdx.x;
    const int base = blockIdx.x * CHUNK;
    int s = 0;
    #pragma unroll
    for (int j = 0; j < CHUNK / 256; j++) {
        int i = base + j * 256 + t;
        if (i < n) s += deg[i];
    }
    sh[t] = s;
    __syncthreads();
    #pragma unroll
    for (int o = 128; o > 0; o >>= 1) {
        if (t < o) sh[t] += sh[t + o];
        __syncthreads();
    }
    if (t == 0) bsum[blockIdx.x] = sh[0];
}

__global__ void scan_bsum_kernel(int* __restrict__ bsum, int nb)
{
    __shared__ int sh[128];
    const int t = threadIdx.x;
    int v = (t < nb) ? bsum[t] : 0;
    sh[t] = v;
    __syncthreads();
    for (int o = 1; o < 128; o <<= 1) {
        int u = (t >= o) ? sh[t - o] : 0;
        __syncthreads();
        sh[t] += u;
        __syncthreads();
    }
    if (t < nb) bsum[t] = sh[t] - v;        // exclusive
    if (t == nb - 1) bsum[nb] = sh[t];      // total
}

__global__ void write_off_kernel(const int* __restrict__ deg,
                                 const int* __restrict__ bsum,
                                 int* __restrict__ off,
                                 int* __restrict__ cur, int n, int nb)
{
    __shared__ int sh[256];
    const int t = threadIdx.x;
    const int base = blockIdx.x * CHUNK + t * 4;

    int d[4];
    #pragma unroll
    for (int j = 0; j < 4; j++)
        d[j] = (base + j < n) ? deg[base + j] : 0;

    int local = d[0] + d[1] + d[2] + d[3];
    sh[t] = local;
    __syncthreads();
    for (int o = 1; o < 256; o <<= 1) {
        int u = (t >= o) ? sh[t - o] : 0;
        __syncthreads();
        sh[t] += u;
        __syncthreads();
    }
    int run = bsum[blockIdx.x] + sh[t] - local;
    #pragma unroll
    for (int j = 0; j < 4; j++) {
        int i = base + j;
        if (i < n) { off[i] = run; cur[i] = run; run += d[j]; }
    }
    if (blockIdx.x == 0 && t == 0) off[n] = bsum[nb];
}

__global__ void fill_kernel(const int* __restrict__ src, const int* __restrict__ dst,
                            const float* __restrict__ ef,
                            int* __restrict__ cur, int2* __restrict__ srcw, int E)
{
    int e = blockIdx.x * blockDim.x + threadIdx.x;
    if (e < E) {
        int d = dst[e];
        int p = atomicAdd(&cur[d], 1);
        srcw[p] = make_int2(src[e], __float_as_int(ef[e]));
    }
}

// ---------------------------------------------------------------------------
// SpMM gather-reduce over fp16 features: warp per node, fp32 accumulation.
// FUSE_LN: out_h = fp16(relu(LN(acc + h0)))   (feeds layer 1)
// else:    out_f = fp32 acc                    (final output)
// ---------------------------------------------------------------------------
template <bool FUSE_LN>
__global__ void spmm_csr_kernel(const int* __restrict__ off,
                                const int2* __restrict__ srcw,
                                const uint2* __restrict__ hin,
                                const float4* __restrict__ h0,
                                const float* __restrict__ lns,
                                const float* __restrict__ lnb,
                                uint2* __restrict__ out_h,
                                float4* __restrict__ out_f, int n)
{
    const int node = blockIdx.x * 8 + (threadIdx.x >> 5);
    const int lane = threadIdx.x & 31;
    if (node >= n) return;

    const int beg = off[node];
    const int end = off[node + 1];

    float4 a = make_float4(0.f, 0.f, 0.f, 0.f);
    for (int base = beg; base < end; base += 32) {
        int cnt = min(end - base, 32);
        int2 sw = make_int2(0, 0);
        if (lane < cnt) sw = __ldg(&srcw[base + lane]);
        #pragma unroll 4
        for (int j = 0; j < cnt; j++) {
            int   s = __shfl_sync(0xffffffffu, sw.x, j);
            float w = __int_as_float(__shfl_sync(0xffffffffu, sw.y, j));
            uint2 p = __ldg(&hin[(size_t)s * 32 + lane]);
            float2 lo = __half22float2(*(half2*)&p.x);
            float2 hi = __half22float2(*(half2*)&p.y);
            a.x += lo.x * w; a.y += lo.y * w;
            a.z += hi.x * w; a.w += hi.y * w;
        }
    }

    if (FUSE_LN) {
        float4 r = __ldg(&h0[(size_t)node * 32 + lane]);
        a.x += r.x; a.y += r.y; a.z += r.z; a.w += r.w;

        float s = a.x + a.y + a.z + a.w;
        #pragma unroll
        for (int o = 16; o > 0; o >>= 1) s += __shfl_xor_sync(0xffffffffu, s, o);
        float mu = s * (1.f / HID);
        float dx = a.x - mu, dy = a.y - mu, dz = a.z - mu, dw = a.w - mu;
        float q = dx * dx + dy * dy + dz * dz + dw * dw;
        #pragma unroll
        for (int o = 16; o > 0; o >>= 1) q += __shfl_xor_sync(0xffffffffu, q, o);
        float rstd = rsqrtf(q * (1.f / HID) + EPS);

        int j0 = lane * 4;
        float4 sc = __ldg((const float4*)&lns[j0]);
        float4 bi = __ldg((const float4*)&lnb[j0]);
        out_h[(size_t)node * 32 + lane] = pack_h4(
            fmaxf(dx * rstd * sc.x + bi.x, 0.f),
            fmaxf(dy * rstd * sc.y + bi.y, 0.f),
            fmaxf(dz * rstd * sc.z + bi.z, 0.f),
            fmaxf(dw * rstd * sc.w + bi.w, 0.f));
    } else {
        out_f[(size_t)node * 32 + lane] = a;
    }
}

// ---------------------------------------------------------------------------
extern "C" void kernel_launch(void* const* d_in, const int* in_sizes, int n_in,
                              void* d_out, int out_size)
{
    const float* x   = (const float*)d_in[0];
    const int*   ei  = (const int*)d_in[1];     // [2, E] int32
    const float* ef  = (const float*)d_in[2];
    const float* W   = (const float*)d_in[3];
    const float* b   = (const float*)d_in[4];
    const float* lns = (const float*)d_in[5];
    const float* lnb = (const float*)d_in[6];

    const int n = in_sizes[0] / HID;
    const int E = in_sizes[2];
    float4* out = (float4*)d_out;

    float4 *h0; uint2 *act, *act2; int2* srcw; int *off, *cur, *deg, *bsum;
    cudaGetSymbolAddress((void**)&h0,   g_h0);
    cudaGetSymbolAddress((void**)&act,  g_act);
    cudaGetSymbolAddress((void**)&act2, g_act2);
    cudaGetSymbolAddress((void**)&srcw, g_srcw);
    cudaGetSymbolAddress((void**)&off,  g_off);
    cudaGetSymbolAddress((void**)&cur,  g_cur);
    cudaGetSymbolAddress((void**)&deg,  g_deg);
    cudaGetSymbolAddress((void**)&bsum, g_bsum);

    const int nb = (n + CHUNK - 1) / CHUNK;

    // 1. Linear + LN0 + ReLU (fused), act in fp16
    const int gemm_smem = (128 * 132 + 32 * HID) * (int)sizeof(float);
    cudaFuncSetAttribute(gemm_ln_kernel,
                         cudaFuncAttributeMaxDynamicSharedMemorySize, gemm_smem);
    gemm_ln_kernel<<<(n + 31) / 32, 256, gemm_smem>>>(x, W, b, lns, lnb,
                                                      (float*)h0, act, n);

    // 2. CSR build (dst-grouped)
    zero_deg_kernel<<<(n + 255) / 256, 256>>>(deg, n);
    hist_kernel<<<(E + 255) / 256, 256>>>(ei + E, deg, E);
    reduce_kernel<<<nb, 256>>>(deg, bsum, n);
    scan_bsum_kernel<<<1, 128>>>(bsum, nb);
    write_off_kernel<<<nb, 256>>>(deg, bsum, off, cur, n, nb);
    fill_kernel<<<(E + 255) / 256, 256>>>(ei, ei + E, ef, cur, srcw, E);

    // 3. Layer 0 aggregation + residual + LN1 + ReLU (fused), act2 in fp16
    const int spmm_blocks = (n + 7) / 8;
    spmm_csr_kernel<true><<<spmm_blocks, 256>>>(off, srcw, act, h0,
                                                lns + HID, lnb + HID,
                                                act2, nullptr, n);

    // 4. Layer 1 aggregation -> final fp32 output
    spmm_csr_kernel<false><<<spmm_blocks, 256>>>(off, srcw, act2, nullptr,
                                                 nullptr, nullptr,
                                                 nullptr, out, n);
}

// round 8
// speedup vs baseline: 1.9779x; 1.0738x over previous
#include <cuda_runtime.h>
#include <cuda_fp16.h>

#define NMAX 100000
#define EMAX 1600000
#define HID 128
#define EPS 1e-5f
#define CHUNK 1024
#define NBLK ((NMAX + CHUNK - 1) / CHUNK)   // 98

// Scratch (no cudaMalloc allowed).
__device__ float4 g_h0  [(size_t)NMAX * HID / 4];  // post-linear ("ori"), fp32
__device__ uint2  g_act [(size_t)NMAX * HID / 4];  // layer-0 input, fp16
__device__ uint2  g_act2[(size_t)NMAX * HID / 4];  // layer-1 input, fp16
__device__ int2   g_srcw[EMAX];                    // CSR payload: (src, w-bits)
__device__ int    g_off [NMAX + 1];
__device__ int    g_cur [NMAX];
__device__ int    g_deg [NMAX];
__device__ int    g_bsum[NBLK + 1];

__device__ __forceinline__ uint2 pack_h4(float a, float b, float c, float d)
{
    uint2 r;
    half2 lo = __floats2half2_rn(a, b);
    half2 hi = __floats2half2_rn(c, d);
    r.x = *(unsigned*)&lo;
    r.y = *(unsigned*)&hi;
    return r;
}

// ---------------------------------------------------------------------------
// GEMM + bias + fused LN0 + ReLU.  64 rows/block, 512 threads (16 warps x 4
// rows).  Halves per-block W reload traffic vs 32-row blocks (200MB -> 100MB
// of L2 reads for W).  Extra trailing blocks zero the degree array (fused
// zero_deg launch).
// ---------------------------------------------------------------------------
extern __shared__ float smem_dyn[];
__global__ void gemm_ln_kernel(const float* __restrict__ x,
                               const float* __restrict__ W,
                               const float* __restrict__ b,
                               const float* __restrict__ lns,
                               const float* __restrict__ lnb,
                               float* __restrict__ h0,
                               uint2* __restrict__ act,
                               int* __restrict__ deg,
                               int n, int gemm_blocks)
{
    // Fused degree-zeroing blocks
    if (blockIdx.x >= gemm_blocks) {
        int zb = blockIdx.x - gemm_blocks;
        int i = zb * CHUNK + threadIdx.x;
        if (i < n) deg[i] = 0;
        i += 512;
        if (i < n) deg[i] = 0;
        return;
    }

    float4* Ws4 = (float4*)smem_dyn;            // [128][33] float4 (stride 132 f)
    float*  xs  = smem_dyn + 128 * 132;         // 64 rows * 128
    const int tid  = threadIdx.x;
    const int lane = tid & 31;
    const int warp = tid >> 5;                  // 0..15
    const int row0 = blockIdx.x * 64;

    for (int idx = tid; idx < HID * HID; idx += 512) {
        int j = idx >> 7, k = idx & 127;
        smem_dyn[k * 132 + j] = W[idx];
    }
    for (int idx = tid; idx < 64 * HID; idx += 512) {
        int r = idx >> 7, k = idx & 127;
        int row = row0 + r;
        xs[r * HID + k] = (row < n) ? x[(size_t)row * HID + k] : 0.f;
    }
    __syncthreads();

    const int r0 = warp * 4;
    float acc[4][4];
    #pragma unroll
    for (int i = 0; i < 4; i++)
        #pragma unroll
        for (int c = 0; c < 4; c++) acc[i][c] = 0.f;

    #pragma unroll 2
    for (int k0 = 0; k0 < HID; k0 += 4) {
        float4 w0 = Ws4[(k0 + 0) * 33 + lane];
        float4 w1 = Ws4[(k0 + 1) * 33 + lane];
        float4 w2 = Ws4[(k0 + 2) * 33 + lane];
        float4 w3 = Ws4[(k0 + 3) * 33 + lane];
        #pragma unroll
        for (int i = 0; i < 4; i++) {
            float4 xv = *(const float4*)&xs[(r0 + i) * HID + k0];
            acc[i][0] += xv.x * w0.x; acc[i][0] += xv.y * w1.x;
            acc[i][0] += xv.z * w2.x; acc[i][0] += xv.w * w3.x;
            acc[i][1] += xv.x * w0.y; acc[i][1] += xv.y * w1.y;
            acc[i][1] += xv.z * w2.y; acc[i][1] += xv.w * w3.y;
            acc[i][2] += xv.x * w0.z; acc[i][2] += xv.y * w1.z;
            acc[i][2] += xv.z * w2.z; acc[i][2] += xv.w * w3.z;
            acc[i][3] += xv.x * w0.w; acc[i][3] += xv.y * w1.w;
            acc[i][3] += xv.z * w2.w; acc[i][3] += xv.w * w3.w;
        }
    }

    const int j0 = lane * 4;
    float4 bv = *(const float4*)&b[j0];
    float4 sc = *(const float4*)&lns[j0];
    float4 bi = *(const float4*)&lnb[j0];

    #pragma unroll
    for (int i = 0; i < 4; i++) {
        int row = row0 + r0 + i;
        if (row < n) {
            float4 h;
            h.x = acc[i][0] + bv.x; h.y = acc[i][1] + bv.y;
            h.z = acc[i][2] + bv.z; h.w = acc[i][3] + bv.w;
            *(float4*)&h0[(size_t)row * HID + j0] = h;

            float s = h.x + h.y + h.z + h.w;
            #pragma unroll
            for (int o = 16; o > 0; o >>= 1) s += __shfl_xor_sync(0xffffffffu, s, o);
            float mu = s * (1.f / HID);
            float dx = h.x - mu, dy = h.y - mu, dz = h.z - mu, dw = h.w - mu;
            float q = dx * dx + dy * dy + dz * dz + dw * dw;
            #pragma unroll
            for (int o = 16; o > 0; o >>= 1) q += __shfl_xor_sync(0xffffffffu, q, o);
            float rstd = rsqrtf(q * (1.f / HID) + EPS);

            act[(size_t)row * 32 + lane] = pack_h4(
                fmaxf(dx * rstd * sc.x + bi.x, 0.f),
                fmaxf(dy * rstd * sc.y + bi.y, 0.f),
                fmaxf(dz * rstd * sc.z + bi.z, 0.f),
                fmaxf(dw * rstd * sc.w + bi.w, 0.f));
        }
    }
}

// ---------------------------------------------------------------------------
// CSR build
// ---------------------------------------------------------------------------
__global__ void hist_kernel(const int* __restrict__ dst, int* __restrict__ deg, int E)
{
    int e0 = (blockIdx.x * blockDim.x + threadIdx.x) * 4;
    if (e0 + 3 < E) {
        int4 d = *(const int4*)&dst[e0];
        atomicAdd(&deg[d.x], 1); atomicAdd(&deg[d.y], 1);
        atomicAdd(&deg[d.z], 1); atomicAdd(&deg[d.w], 1);
    } else {
        for (int e = e0; e < E; e++) atomicAdd(&deg[dst[e]], 1);
    }
}

__global__ void reduce_kernel(const int* __restrict__ deg,
                              int* __restrict__ bsum, int n)
{
    __shared__ int sh[256];
    const int t = threadIdx.x;
    const int base = blockIdx.x * CHUNK;
    int s = 0;
    #pragma unroll
    for (int j = 0; j < CHUNK / 256; j++) {
        int i = base + j * 256 + t;
        if (i < n) s += deg[i];
    }
    sh[t] = s;
    __syncthreads();
    #pragma unroll
    for (int o = 128; o > 0; o >>= 1) {
        if (t < o) sh[t] += sh[t + o];
        __syncthreads();
    }
    if (t == 0) bsum[blockIdx.x] = sh[0];
}

__global__ void scan_bsum_kernel(int* __restrict__ bsum, int nb)
{
    __shared__ int sh[128];
    const int t = threadIdx.x;
    int v = (t < nb) ? bsum[t] : 0;
    sh[t] = v;
    __syncthreads();
    for (int o = 1; o < 128; o <<= 1) {
        int u = (t >= o) ? sh[t - o] : 0;
        __syncthreads();
        sh[t] += u;
        __syncthreads();
    }
    if (t < nb) bsum[t] = sh[t] - v;        // exclusive
    if (t == nb - 1) bsum[nb] = sh[t];      // total
}

__global__ void write_off_kernel(const int* __restrict__ deg,
                                 const int* __restrict__ bsum,
                                 int* __restrict__ off,
                                 int* __restrict__ cur, int n, int nb)
{
    __shared__ int sh[256];
    const int t = threadIdx.x;
    const int base = blockIdx.x * CHUNK + t * 4;

    int d[4];
    #pragma unroll
    for (int j = 0; j < 4; j++)
        d[j] = (base + j < n) ? deg[base + j] : 0;

    int local = d[0] + d[1] + d[2] + d[3];
    sh[t] = local;
    __syncthreads();
    for (int o = 1; o < 256; o <<= 1) {
        int u = (t >= o) ? sh[t - o] : 0;
        __syncthreads();
        sh[t] += u;
        __syncthreads();
    }
    int run = bsum[blockIdx.x] + sh[t] - local;
    #pragma unroll
    for (int j = 0; j < 4; j++) {
        int i = base + j;
        if (i < n) { off[i] = run; cur[i] = run; run += d[j]; }
    }
    if (blockIdx.x == 0 && t == 0) off[n] = bsum[nb];
}

__global__ void fill_kernel(const int* __restrict__ src, const int* __restrict__ dst,
                            const float* __restrict__ ef,
                            int* __restrict__ cur, int2* __restrict__ srcw, int E)
{
    int e0 = (blockIdx.x * blockDim.x + threadIdx.x) * 4;
    if (e0 + 3 < E) {
        int4   s = *(const int4*)&src[e0];
        int4   d = *(const int4*)&dst[e0];
        float4 w = *(const float4*)&ef[e0];
        int p0 = atomicAdd(&cur[d.x], 1);
        int p1 = atomicAdd(&cur[d.y], 1);
        int p2 = atomicAdd(&cur[d.z], 1);
        int p3 = atomicAdd(&cur[d.w], 1);
        srcw[p0] = make_int2(s.x, __float_as_int(w.x));
        srcw[p1] = make_int2(s.y, __float_as_int(w.y));
        srcw[p2] = make_int2(s.z, __float_as_int(w.z));
        srcw[p3] = make_int2(s.w, __float_as_int(w.w));
    } else {
        for (int e = e0; e < E; e++) {
            int p = atomicAdd(&cur[dst[e]], 1);
            srcw[p] = make_int2(src[e], __float_as_int(ef[e]));
        }
    }
}

// ---------------------------------------------------------------------------
// SpMM gather-reduce over fp16 features: warp per node, fp32 accumulation.
// unroll 8 -> 8 independent LDG.64s in flight per warp.
// ---------------------------------------------------------------------------
template <bool FUSE_LN>
__global__ void spmm_csr_kernel(const int* __restrict__ off,
                                const int2* __restrict__ srcw,
                                const uint2* __restrict__ hin,
                                const float4* __restrict__ h0,
                                const float* __restrict__ lns,
                                const float* __restrict__ lnb,
                                uint2* __restrict__ out_h,
                                float4* __restrict__ out_f, int n)
{
    const int node = blockIdx.x * 8 + (threadIdx.x >> 5);
    const int lane = threadIdx.x & 31;
    if (node >= n) return;

    const int beg = off[node];
    const int end = off[node + 1];

    float4 a = make_float4(0.f, 0.f, 0.f, 0.f);
    for (int base = beg; base < end; base += 32) {
        int cnt = min(end - base, 32);
        int2 sw = make_int2(0, 0);
        if (lane < cnt) sw = __ldg(&srcw[base + lane]);
        #pragma unroll 8
        for (int j = 0; j < cnt; j++) {
            int   s = __shfl_sync(0xffffffffu, sw.x, j);
            float w = __int_as_float(__shfl_sync(0xffffffffu, sw.y, j));
            uint2 p = __ldg(&hin[(size_t)s * 32 + lane]);
            float2 lo = __half22float2(*(half2*)&p.x);
            float2 hi = __half22float2(*(half2*)&p.y);
            a.x += lo.x * w; a.y += lo.y * w;
            a.z += hi.x * w; a.w += hi.y * w;
        }
    }

    if (FUSE_LN) {
        float4 r = __ldg(&h0[(size_t)node * 32 + lane]);
        a.x += r.x; a.y += r.y; a.z += r.z; a.w += r.w;

        float s = a.x + a.y + a.z + a.w;
        #pragma unroll
        for (int o = 16; o > 0; o >>= 1) s += __shfl_xor_sync(0xffffffffu, s, o);
        float mu = s * (1.f / HID);
        float dx = a.x - mu, dy = a.y - mu, dz = a.z - mu, dw = a.w - mu;
        float q = dx * dx + dy * dy + dz * dz + dw * dw;
        #pragma unroll
        for (int o = 16; o > 0; o >>= 1) q += __shfl_xor_sync(0xffffffffu, q, o);
        float rstd = rsqrtf(q * (1.f / HID) + EPS);

        int j0 = lane * 4;
        float4 sc = __ldg((const float4*)&lns[j0]);
        float4 bi = __ldg((const float4*)&lnb[j0]);
        out_h[(size_t)node * 32 + lane] = pack_h4(
            fmaxf(dx * rstd * sc.x + bi.x, 0.f),
            fmaxf(dy * rstd * sc.y + bi.y, 0.f),
            fmaxf(dz * rstd * sc.z + bi.z, 0.f),
            fmaxf(dw * rstd * sc.w + bi.w, 0.f));
    } else {
        out_f[(size_t)node * 32 + lane] = a;
    }
}

// ---------------------------------------------------------------------------
extern "C" void kernel_launch(void* const* d_in, const int* in_sizes, int n_in,
                              void* d_out, int out_size)
{
    const float* x   = (const float*)d_in[0];
    const int*   ei  = (const int*)d_in[1];     // [2, E] int32
    const float* ef  = (const float*)d_in[2];
    const float* W   = (const float*)d_in[3];
    const float* b   = (const float*)d_in[4];
    const float* lns = (const float*)d_in[5];
    const float* lnb = (const float*)d_in[6];

    const int n = in_sizes[0] / HID;
    const int E = in_sizes[2];
    float4* out = (float4*)d_out;

    float4 *h0; uint2 *act, *act2; int2* srcw; int *off, *cur, *deg, *bsum;
    cudaGetSymbolAddress((void**)&h0,   g_h0);
    cudaGetSymbolAddress((void**)&act,  g_act);
    cudaGetSymbolAddress((void**)&act2, g_act2);
    cudaGetSymbolAddress((void**)&srcw, g_srcw);
    cudaGetSymbolAddress((void**)&off,  g_off);
    cudaGetSymbolAddress((void**)&cur,  g_cur);
    cudaGetSymbolAddress((void**)&deg,  g_deg);
    cudaGetSymbolAddress((void**)&bsum, g_bsum);

    const int nb = (n + CHUNK - 1) / CHUNK;

    // 1. Linear + LN0 + ReLU (fused) with fused deg-zeroing blocks
    const int gemm_blocks = (n + 63) / 64;
    const int gemm_smem = (128 * 132 + 64 * HID) * (int)sizeof(float); // 100352 B
    cudaFuncSetAttribute(gemm_ln_kernel,
                         cudaFuncAttributeMaxDynamicSharedMemorySize, gemm_smem);
    gemm_ln_kernel<<<gemm_blocks + nb, 512, gemm_smem>>>(x, W, b, lns, lnb,
                                                         (float*)h0, act, deg,
                                                         n, gemm_blocks);

    // 2. CSR build (dst-grouped)
    hist_kernel<<<(E / 4 + 255) / 256, 256>>>(ei + E, deg, E);
    reduce_kernel<<<nb, 256>>>(deg, bsum, n);
    scan_bsum_kernel<<<1, 128>>>(bsum, nb);
    write_off_kernel<<<nb, 256>>>(deg, bsum, off, cur, n, nb);
    fill_kernel<<<(E / 4 + 255) / 256, 256>>>(ei, ei + E, ef, cur, srcw, E);

    // 3. Layer 0 aggregation + residual + LN1 + ReLU (fused), act2 in fp16
    const int spmm_blocks = (n + 7) / 8;
    spmm_csr_kernel<true><<<spmm_blocks, 256>>>(off, srcw, act, h0,
                                                lns + HID, lnb + HID,
                                                act2, nullptr, n);

    // 4. Layer 1 aggregation -> final fp32 output
    spmm_csr_kernel<false><<<spmm_blocks, 256>>>(off, srcw, act2, nullptr,
                                                 nullptr, nullptr,
                                                 nullptr, out, n);
}